// round 16
// baseline (speedup 1.0000x reference)
#include <cuda_runtime.h>
#include <cuda_fp16.h>
#include <math.h>
#include <stdint.h>

// Problem constants (fixed by the reference)
#define HIDDEN 2048
#define NHEADS 16
#define HEADDIM 128
#define BATCH 2
#define SEQ 2048
#define MTOK (BATCH * SEQ)   // 4096

// ---------------------------------------------------------------------------
// Scratch buffers (allocation-free rule: __device__ globals)
// ---------------------------------------------------------------------------
__device__ __half g_q[MTOK * HIDDEN];        // fp16 Q (pre-scaled)
__device__ __half g_k[MTOK * HIDDEN];        // fp16 K
__device__ __half g_v[MTOK * HIDDEN];        // fp16 V
__device__ __half g_ao[MTOK * HIDDEN];       // attention out fp16
__device__ __half g_hs[MTOK * HIDDEN];       // fp16 hidden states
__device__ __half g_wq[HIDDEN * HIDDEN];     // fp16(scale*wq)^T  [N][K]
__device__ __half g_wk[HIDDEN * HIDDEN];
__device__ __half g_wv[HIDDEN * HIDDEN];
__device__ __half g_wo[HIDDEN * HIDDEN];
__device__ float  g_bqs[HIDDEN];             // scale * bq

__device__ __forceinline__ void mma_f16(float* c, const uint32_t* a, const uint32_t* b) {
    asm volatile(
        "mma.sync.aligned.m16n8k16.row.col.f32.f16.f16.f32 "
        "{%0,%1,%2,%3}, {%4,%5,%6,%7}, {%8,%9}, {%0,%1,%2,%3};\n"
        : "+f"(c[0]), "+f"(c[1]), "+f"(c[2]), "+f"(c[3])
        : "r"(a[0]), "r"(a[1]), "r"(a[2]), "r"(a[3]), "r"(b[0]), "r"(b[1]));
}

__device__ __forceinline__ void ldsm_x4(uint32_t& r0, uint32_t& r1,
                                        uint32_t& r2, uint32_t& r3, uint32_t addr) {
    asm volatile("ldmatrix.sync.aligned.m8n8.x4.shared.b16 {%0,%1,%2,%3}, [%4];"
                 : "=r"(r0), "=r"(r1), "=r"(r2), "=r"(r3) : "r"(addr));
}

__device__ __forceinline__ void ldsm_x2_trans(uint32_t& r0, uint32_t& r1, uint32_t addr) {
    asm volatile("ldmatrix.sync.aligned.m8n8.x2.trans.shared.b16 {%0,%1}, [%2];"
                 : "=r"(r0), "=r"(r1) : "r"(addr));
}

__device__ __forceinline__ void cp_async16(uint32_t smem_addr, const void* gptr) {
    asm volatile("cp.async.cg.shared.global [%0], [%1], 16;"
                 :: "r"(smem_addr), "l"(gptr));
}
#define CP_COMMIT() asm volatile("cp.async.commit_group;" ::: "memory")
#define CP_WAIT(N)  asm volatile("cp.async.wait_group %0;" :: "n"(N) : "memory")

__device__ __forceinline__ uint32_t smem_u32(const void* p) {
    return (uint32_t)__cvta_generic_to_shared(p);
}

// ---------------------------------------------------------------------------
// Prep kernels
// ---------------------------------------------------------------------------
__global__ void prep_round_half(const float* __restrict__ src,
                                __half* __restrict__ dst,
                                float mul, int n4)
{
    int i = blockIdx.x * blockDim.x + threadIdx.x;
    if (i < n4) {
        float4 v = *(const float4*)(src + i * 4);
        *(__half2*)(dst + i * 4)     = __floats2half2_rn(v.x * mul, v.y * mul);
        *(__half2*)(dst + i * 4 + 2) = __floats2half2_rn(v.z * mul, v.w * mul);
    }
}

__global__ void prep_scale_kernel(const float* __restrict__ src,
                                  float* __restrict__ dst,
                                  float mul, int n4)
{
    int i = blockIdx.x * blockDim.x + threadIdx.x;
    if (i < n4) {
        float4 v = *(const float4*)(src + i * 4);
        float4 o = { v.x * mul, v.y * mul, v.z * mul, v.w * mul };
        *(float4*)(dst + i * 4) = o;
    }
}

// W[K][N] -> Wt[N][K] fp16 (with optional scale)
__global__ void prep_transpose_half(const float* __restrict__ src,
                                    __half* __restrict__ dst, float mul)
{
    __shared__ float t[32][33];
    int bx = blockIdx.x * 32, by = blockIdx.y * 32;
    int tx = threadIdx.x, ty = threadIdx.y;
#pragma unroll
    for (int j = 0; j < 4; j++)
        t[ty + 8 * j][tx] = src[(size_t)(by + ty + 8 * j) * HIDDEN + bx + tx];
    __syncthreads();
#pragma unroll
    for (int j = 0; j < 4; j++)
        dst[(size_t)(bx + ty + 8 * j) * HIDDEN + by + tx] =
            __float2half_rn(t[tx][ty + 8 * j] * mul);
}

// ---------------------------------------------------------------------------
// FP16 tensor-core GEMM: C = A[M,K](f16) @ Wt[N,K](f16)^T + bias  (unchanged)
// ---------------------------------------------------------------------------
#define GBM 128
#define GBN 128
#define GBK 64
#define GRS 36
#define GRB (GRS * 4)                      // 144 B row stride
#define G_STG_WORDS (GBM * GRS)
#define GEMM_SMEM_BYTES (4 * G_STG_WORDS * 4)   // 73728

__global__ __launch_bounds__(256, 2)
void gemm_f16_kernel(const __half* __restrict__ A,
                     const __half* __restrict__ Wt,
                     const float* __restrict__ bias,
                     float* __restrict__ Cf,
                     __half* __restrict__ Ch)
{
    extern __shared__ uint32_t gsm[];
    uint32_t* Asm = gsm;
    uint32_t* Bsm = gsm + 2 * G_STG_WORDS;
    const uint32_t as_u32 = smem_u32(Asm);
    const uint32_t bs_u32 = smem_u32(Bsm);

    const int tid  = threadIdx.x;
    const int lane = tid & 31;
    const int warp = tid >> 5;
    const int wm   = warp >> 2;
    const int wn   = warp & 3;
    const int g    = lane >> 2;
    const int tig  = lane & 3;

    const int bm = blockIdx.y * GBM;
    const int bn = blockIdx.x * GBN;

    const int gl      = lane & 7;
    const int a_roff  = ((lane >> 3) & 1) * 8 + gl;
    const int a_coff  = (lane >> 4) * 16;
    const int b_roff  = (lane >> 4) * 8 + gl;
    const int b_coff  = ((lane >> 3) & 1) * 16;

    const int f_row = tid >> 1;
    const int f_ch0 = (tid & 1) * 4;

    auto fill = [&](int kt) {
        const int s = kt & 1;
        const __half* Ag = A  + (size_t)bm * HIDDEN + kt * GBK;
        const __half* Bg = Wt + (size_t)bn * HIDDEN + kt * GBK;
        const uint32_t abase = as_u32 + s * G_STG_WORDS * 4;
        const uint32_t bbase = bs_u32 + s * G_STG_WORDS * 4;
#pragma unroll
        for (int c = 0; c < 4; c++) {
            int ch = f_ch0 + c;
            cp_async16(abase + f_row * GRB + ch * 16,
                       Ag + (size_t)f_row * HIDDEN + ch * 8);
            cp_async16(bbase + f_row * GRB + ch * 16,
                       Bg + (size_t)f_row * HIDDEN + ch * 8);
        }
        CP_COMMIT();
    };

    float acc[4][4][4];
#pragma unroll
    for (int mi = 0; mi < 4; mi++)
#pragma unroll
        for (int ni = 0; ni < 4; ni++)
#pragma unroll
            for (int r = 0; r < 4; r++) acc[mi][ni][r] = 0.0f;

    const int nk = HIDDEN / GBK;   // 32
    fill(0);

    for (int kt = 0; kt < nk; kt++) {
        if (kt + 1 < nk) { fill(kt + 1); CP_WAIT(1); }
        else             { CP_WAIT(0); }
        __syncthreads();

        const uint32_t abase = as_u32 + (kt & 1) * G_STG_WORDS * 4;
        const uint32_t bbase = bs_u32 + (kt & 1) * G_STG_WORDS * 4;
#pragma unroll
        for (int ks = 0; ks < 4; ks++) {
            const int kb = ks * 32;
            uint32_t af[4][4], bf[4][2];
#pragma unroll
            for (int mi = 0; mi < 4; mi++) {
                int m = wm * 64 + mi * 16;
                ldsm_x4(af[mi][0], af[mi][1], af[mi][2], af[mi][3],
                        abase + (m + a_roff) * GRB + kb + a_coff);
            }
#pragma unroll
            for (int p = 0; p < 2; p++) {
                int n = wn * 32 + p * 16;
                ldsm_x4(bf[2 * p][0], bf[2 * p][1], bf[2 * p + 1][0], bf[2 * p + 1][1],
                        bbase + (n + b_roff) * GRB + kb + b_coff);
            }
#pragma unroll
            for (int mi = 0; mi < 4; mi++)
#pragma unroll
                for (int ni = 0; ni < 4; ni++)
                    mma_f16(acc[mi][ni], af[mi], bf[ni]);
        }
        __syncthreads();
    }

#pragma unroll
    for (int ni = 0; ni < 4; ni++) {
        int col = bn + wn * 32 + ni * 8 + tig * 2;
        float b0 = bias[col], b1 = bias[col + 1];
#pragma unroll
        for (int mi = 0; mi < 4; mi++) {
            int row = bm + wm * 64 + mi * 16 + g;
            float v00 = acc[mi][ni][0] + b0, v01 = acc[mi][ni][1] + b1;
            float v10 = acc[mi][ni][2] + b0, v11 = acc[mi][ni][3] + b1;
            if (Ch) {
                *(__half2*)(Ch + (size_t)row * HIDDEN + col)       = __floats2half2_rn(v00, v01);
                *(__half2*)(Ch + (size_t)(row + 8) * HIDDEN + col) = __floats2half2_rn(v10, v11);
            } else {
                float2 r0 = { v00, v01 };
                float2 r1 = { v10, v11 };
                *(float2*)(Cf + (size_t)row * HIDDEN + col)       = r0;
                *(float2*)(Cf + (size_t)(row + 8) * HIDDEN + col) = r1;
            }
        }
    }
}

// ---------------------------------------------------------------------------
// FP16 flash attention, BQ=64, 256 threads, 2 CTAs/SM (ping-pong overlap).
// S: warp grid 2x4, tile 32x16.  PV: warp grid 2x4, tile 32x32.
// ---------------------------------------------------------------------------
#define ABQ 64
#define ABKV 64
#define LQK 68    // Q/K/V row stride, u32 words (272 B)
#define LVW 68
#define LPW 36    // P row stride (144 B)

#define AS_QS 0
#define AS_KS (AS_QS + ABQ * LQK)         // 4352
#define AS_VS (AS_KS + ABKV * LQK)        // 8704
#define AS_PS (AS_VS + ABKV * LVW)        // 13056
#define AS_MB (AS_PS + ABQ * LPW)         // 15360  maxbuf[4][64]
#define AS_LB (AS_MB + 4 * ABQ)           // 15616  lbuf[4][64]
#define AS_TOT (AS_LB + 4 * ABQ)          // 15872 words
#define ATTN_SMEM_BYTES (AS_TOT * 4)      // 63488 B -> 2 CTAs/SM

__global__ __launch_bounds__(256, 2)
void attn_f16_kernel(const __half* __restrict__ Q,
                     const __half* __restrict__ K,
                     const __half* __restrict__ V,
                     __half* __restrict__ O)
{
    extern __shared__ float sm[];
    uint32_t* Pu = (uint32_t*)(sm + AS_PS);
    float* maxbuf = sm + AS_MB;
    float* lbuf   = sm + AS_LB;
    const uint32_t qs_u32 = smem_u32(sm + AS_QS);
    const uint32_t ks_u32 = smem_u32(sm + AS_KS);
    const uint32_t vs_u32 = smem_u32(sm + AS_VS);
    const uint32_t ps_u32 = smem_u32(sm + AS_PS);

    const int tid  = threadIdx.x;
    const int lane = tid & 31;
    const int warp = tid >> 5;
    const int g    = lane >> 2;
    const int tig  = lane & 3;
    const int wm   = warp >> 2;    // 0..1 -> q rows wm*32
    const int wn   = warp & 3;     // 0..3 -> 16-col kv slab (S) / 32-col d slab (PV)

    const int q0 = blockIdx.x * ABQ;
    const int h  = blockIdx.y;
    const int b  = blockIdx.z;
    const size_t base = (size_t)b * SEQ * HIDDEN + (size_t)h * HEADDIM;

    const int rowA0 = wm * 32 + g;
    float mreg[4] = { -INFINITY, -INFINITY, -INFINITY, -INFINITY };
    float lreg[4] = { 0.0f, 0.0f, 0.0f, 0.0f };

    const int gl     = lane & 7;
    const int a_roff = ((lane >> 3) & 1) * 8 + gl;
    const int a_coff = (lane >> 4) * 16;
    const int b_roff = (lane >> 4) * 8 + gl;
    const int b_coff = ((lane >> 3) & 1) * 16;

    // loads: 64 rows x 16 chunks = 1024 chunks / 256 thr = 4 each
    const int krow = tid >> 2, kch0 = (tid & 3) * 4;

    // ---- prologue: Q, K(0), V(0) ----
#pragma unroll
    for (int c = 0; c < 4; c++)
        cp_async16(qs_u32 + krow * (LQK * 4) + (kch0 + c) * 16,
                   Q + base + (size_t)(q0 + krow) * HIDDEN + (kch0 + c) * 8);
    CP_COMMIT();
#pragma unroll
    for (int c = 0; c < 4; c++)
        cp_async16(ks_u32 + krow * (LQK * 4) + (kch0 + c) * 16,
                   K + base + (size_t)krow * HIDDEN + (kch0 + c) * 8);
    CP_COMMIT();
#pragma unroll
    for (int c = 0; c < 4; c++)
        cp_async16(vs_u32 + krow * (LVW * 4) + (kch0 + c) * 16,
                   V + base + (size_t)krow * HIDDEN + (kch0 + c) * 8);
    CP_COMMIT();

    float o[2][4][4];
#pragma unroll
    for (int mi = 0; mi < 2; mi++)
#pragma unroll
        for (int nj = 0; nj < 4; nj++)
#pragma unroll
            for (int r = 0; r < 4; r++) o[mi][nj][r] = 0.0f;

    const int NT = SEQ / ABKV;   // 32
    for (int t = 0; t < NT; t++) {
        CP_WAIT(1);
        __syncthreads();

        // ---- S = Q @ K^T : warp tile 32x16, 8 k-steps ----
        float sacc[2][2][4];
#pragma unroll
        for (int mi = 0; mi < 2; mi++)
#pragma unroll
            for (int ni = 0; ni < 2; ni++)
#pragma unroll
                for (int r = 0; r < 4; r++) sacc[mi][ni][r] = 0.0f;

#pragma unroll
        for (int ks = 0; ks < 8; ks++) {
            const int kb = ks * 32;
            uint32_t af[2][4], bf[2][2];
#pragma unroll
            for (int mi = 0; mi < 2; mi++) {
                int m = wm * 32 + mi * 16;
                ldsm_x4(af[mi][0], af[mi][1], af[mi][2], af[mi][3],
                        qs_u32 + (m + a_roff) * (LQK * 4) + kb + a_coff);
            }
            {
                int n = wn * 16;
                ldsm_x4(bf[0][0], bf[0][1], bf[1][0], bf[1][1],
                        ks_u32 + (n + b_roff) * (LQK * 4) + kb + b_coff);
            }
#pragma unroll
            for (int mi = 0; mi < 2; mi++)
#pragma unroll
                for (int ni = 0; ni < 2; ni++)
                    mma_f16(sacc[mi][ni], af[mi], bf[ni]);
        }

        // ---- warp-local row maxes ----
#pragma unroll
        for (int mi = 0; mi < 2; mi++) {
            float a = -INFINITY, c = -INFINITY;
#pragma unroll
            for (int ni = 0; ni < 2; ni++) {
                a = fmaxf(a, fmaxf(sacc[mi][ni][0], sacc[mi][ni][1]));
                c = fmaxf(c, fmaxf(sacc[mi][ni][2], sacc[mi][ni][3]));
            }
            a = fmaxf(a, __shfl_xor_sync(0xFFFFFFFF, a, 1));
            a = fmaxf(a, __shfl_xor_sync(0xFFFFFFFF, a, 2));
            c = fmaxf(c, __shfl_xor_sync(0xFFFFFFFF, c, 1));
            c = fmaxf(c, __shfl_xor_sync(0xFFFFFFFF, c, 2));
            if (tig == 0) {
                maxbuf[wn * ABQ + rowA0 + mi * 16]     = a;
                maxbuf[wn * ABQ + rowA0 + mi * 16 + 8] = c;
            }
        }
        __syncthreads();   // Ks consumed + maxbuf visible

        // ---- prefetch K(t+1) ----
        if (t + 1 < NT) {
            const __half* Kn = K + base + (size_t)(t + 1) * ABKV * HIDDEN;
#pragma unroll
            for (int c = 0; c < 4; c++)
                cp_async16(ks_u32 + krow * (LQK * 4) + (kch0 + c) * 16,
                           Kn + (size_t)krow * HIDDEN + (kch0 + c) * 8);
            CP_COMMIT();
        }

        // ---- softmax: combine maxes (4 slabs), exp, write P (fp16) ----
        float sc[4], lsum[4];
#pragma unroll
        for (int i = 0; i < 4; i++) {
            int row = rowA0 + (i >> 1) * 16 + (i & 1) * 8;
            float mn = fmaxf(fmaxf(maxbuf[row], maxbuf[ABQ + row]),
                             fmaxf(maxbuf[2 * ABQ + row], maxbuf[3 * ABQ + row]));
            mn = fmaxf(mreg[i], mn);
            sc[i] = __expf(mreg[i] - mn);
            mreg[i] = mn;
            lsum[i] = 0.0f;
        }
#pragma unroll
        for (int mi = 0; mi < 2; mi++) {
            int rA = rowA0 + mi * 16;
#pragma unroll
            for (int ni = 0; ni < 2; ni++) {
                int cw = wn * 8 + ni * 4 + tig;
                __half2 h0 = __floats2half2_rn(__expf(sacc[mi][ni][0] - mreg[mi * 2]),
                                               __expf(sacc[mi][ni][1] - mreg[mi * 2]));
                __half2 h1 = __floats2half2_rn(__expf(sacc[mi][ni][2] - mreg[mi * 2 + 1]),
                                               __expf(sacc[mi][ni][3] - mreg[mi * 2 + 1]));
                float2 f0 = __half22float2(h0);
                float2 f1 = __half22float2(h1);
                lsum[mi * 2]     += f0.x + f0.y;
                lsum[mi * 2 + 1] += f1.x + f1.y;
                Pu[rA * LPW + cw]       = *(uint32_t*)&h0;
                Pu[(rA + 8) * LPW + cw] = *(uint32_t*)&h1;
            }
        }
#pragma unroll
        for (int i = 0; i < 4; i++) {
            float ls = lsum[i];
            ls += __shfl_xor_sync(0xFFFFFFFF, ls, 1);
            ls += __shfl_xor_sync(0xFFFFFFFF, ls, 2);
            lsum[i] = ls;
        }
        if (tig == 0) {
#pragma unroll
            for (int i = 0; i < 4; i++) {
                int row = rowA0 + (i >> 1) * 16 + (i & 1) * 8;
                lbuf[wn * ABQ + row] = lsum[i];
            }
        }

        if (t + 1 < NT) { CP_WAIT(1); } else { CP_WAIT(0); }
        __syncthreads();   // P + lbuf visible, Vs(t) resident

#pragma unroll
        for (int i = 0; i < 4; i++) {
            int row = rowA0 + (i >> 1) * 16 + (i & 1) * 8;
            lreg[i] = lreg[i] * sc[i] + lbuf[row] + lbuf[ABQ + row]
                    + lbuf[2 * ABQ + row] + lbuf[3 * ABQ + row];
        }

        // ---- O rescale + O += P @ V : warp tile 32x32, 4 k-steps ----
#pragma unroll
        for (int mi = 0; mi < 2; mi++) {
            float s0 = sc[mi * 2], s1 = sc[mi * 2 + 1];
#pragma unroll
            for (int nj = 0; nj < 4; nj++) {
                o[mi][nj][0] *= s0; o[mi][nj][1] *= s0;
                o[mi][nj][2] *= s1; o[mi][nj][3] *= s1;
            }
        }
#pragma unroll
        for (int ks = 0; ks < 4; ks++) {
            const int kb = ks * 32;
            const int kv0 = ks * 16;
            uint32_t af[2][4], bf[4][2];
#pragma unroll
            for (int mi = 0; mi < 2; mi++) {
                int m = wm * 32 + mi * 16;
                ldsm_x4(af[mi][0], af[mi][1], af[mi][2], af[mi][3],
                        ps_u32 + (m + a_roff) * (LPW * 4) + kb + a_coff);
            }
            const uint32_t vrow_addr = vs_u32 + (kv0 + (lane & 15)) * (LVW * 4);
#pragma unroll
            for (int nj = 0; nj < 4; nj++) {
                int n = wn * 32 + nj * 8;
                ldsm_x2_trans(bf[nj][0], bf[nj][1], vrow_addr + n * 2);
            }
#pragma unroll
            for (int mi = 0; mi < 2; mi++)
#pragma unroll
                for (int nj = 0; nj < 4; nj++)
                    mma_f16(o[mi][nj], af[mi], bf[nj]);
        }
        __syncthreads();   // Vs consumed

        // ---- prefetch V(t+1) ----
        if (t + 1 < NT) {
            const __half* Vn = V + base + (size_t)(t + 1) * ABKV * HIDDEN;
#pragma unroll
            for (int c = 0; c < 4; c++)
                cp_async16(vs_u32 + krow * (LVW * 4) + (kch0 + c) * 16,
                           Vn + (size_t)krow * HIDDEN + (kch0 + c) * 8);
            CP_COMMIT();
        }
    }

    // ---- Epilogue: normalize, store fp16 ----
#pragma unroll
    for (int mi = 0; mi < 2; mi++) {
        int r0 = wm * 32 + mi * 16 + g;
        float inv0 = 1.0f / lreg[mi * 2];
        float inv1 = 1.0f / lreg[mi * 2 + 1];
#pragma unroll
        for (int nj = 0; nj < 4; nj++) {
            int col = wn * 32 + nj * 8 + tig * 2;
            __half2 a = __floats2half2_rn(o[mi][nj][0] * inv0, o[mi][nj][1] * inv0);
            __half2 c = __floats2half2_rn(o[mi][nj][2] * inv1, o[mi][nj][3] * inv1);
            *(__half2*)(O + base + (size_t)(q0 + r0) * HIDDEN + col)     = a;
            *(__half2*)(O + base + (size_t)(q0 + r0 + 8) * HIDDEN + col) = c;
        }
    }
}

// ---------------------------------------------------------------------------
// Launch
// ---------------------------------------------------------------------------
extern "C" void kernel_launch(void* const* d_in, const int* in_sizes, int n_in,
                              void* d_out, int out_size)
{
    (void)in_sizes; (void)n_in; (void)out_size;

    const float* hs = (const float*)d_in[0];
    const float* wq = (const float*)d_in[1];
    const float* bq = (const float*)d_in[2];
    const float* wk = (const float*)d_in[3];
    const float* bk = (const float*)d_in[4];
    const float* wv = (const float*)d_in[5];
    const float* bv = (const float*)d_in[6];
    const float* wo = (const float*)d_in[7];
    const float* bo = (const float*)d_in[8];
    float* out = (float*)d_out;

    float *bqs;
    __half *q, *k, *v, *ao, *hsr, *wqr, *wkr, *wvr, *wor;
    cudaGetSymbolAddress((void**)&q,   g_q);
    cudaGetSymbolAddress((void**)&k,   g_k);
    cudaGetSymbolAddress((void**)&v,   g_v);
    cudaGetSymbolAddress((void**)&ao,  g_ao);
    cudaGetSymbolAddress((void**)&hsr, g_hs);
    cudaGetSymbolAddress((void**)&wqr, g_wq);
    cudaGetSymbolAddress((void**)&wkr, g_wk);
    cudaGetSymbolAddress((void**)&wvr, g_wv);
    cudaGetSymbolAddress((void**)&wor, g_wo);
    cudaGetSymbolAddress((void**)&bqs, g_bqs);

    cudaFuncSetAttribute(attn_f16_kernel,
                         cudaFuncAttributeMaxDynamicSharedMemorySize,
                         ATTN_SMEM_BYTES);
    cudaFuncSetAttribute(gemm_f16_kernel,
                         cudaFuncAttributeMaxDynamicSharedMemorySize,
                         GEMM_SMEM_BYTES);

    const float scale = 0.08838834764831845f;  // 1/sqrt(128)

    // ---- prep ----
    const int nh4 = MTOK * HIDDEN / 4;
    prep_round_half<<<nh4 / 256, 256>>>(hs, hsr, 1.0f, nh4);
    dim3 tgrid(HIDDEN / 32, HIDDEN / 32), tblk(32, 8);
    prep_transpose_half<<<tgrid, tblk>>>(wq, wqr, scale);
    prep_transpose_half<<<tgrid, tblk>>>(wk, wkr, 1.0f);
    prep_transpose_half<<<tgrid, tblk>>>(wv, wvr, 1.0f);
    prep_transpose_half<<<tgrid, tblk>>>(wo, wor, 1.0f);
    prep_scale_kernel<<<HIDDEN / 4 / 64, 64>>>(bq, bqs, scale, HIDDEN / 4);

    dim3 gemm_grid(HIDDEN / GBN, MTOK / GBM);   // (16, 32)

    // QKV projections -> fp16 outputs
    gemm_f16_kernel<<<gemm_grid, 256, GEMM_SMEM_BYTES>>>(hsr, wqr, bqs, nullptr, q);
    gemm_f16_kernel<<<gemm_grid, 256, GEMM_SMEM_BYTES>>>(hsr, wkr, bk,  nullptr, k);
    gemm_f16_kernel<<<gemm_grid, 256, GEMM_SMEM_BYTES>>>(hsr, wvr, bv,  nullptr, v);

    dim3 attn_grid(SEQ / ABQ, NHEADS, BATCH);   // (32, 16, 2)
    attn_f16_kernel<<<attn_grid, 256, ATTN_SMEM_BYTES>>>(q, k, v, ao);

    // Output projection -> fp32
    gemm_f16_kernel<<<gemm_grid, 256, GEMM_SMEM_BYTES>>>(ao, wor, bo, out, nullptr);
}

// round 17
// speedup vs baseline: 1.1687x; 1.1687x over previous
#include <cuda_runtime.h>
#include <cuda_fp16.h>
#include <math.h>
#include <stdint.h>

// Problem constants (fixed by the reference)
#define HIDDEN 2048
#define NHEADS 16
#define HEADDIM 128
#define BATCH 2
#define SEQ 2048
#define MTOK (BATCH * SEQ)   // 4096

// ---------------------------------------------------------------------------
// Scratch buffers (allocation-free rule: __device__ globals)
// ---------------------------------------------------------------------------
__device__ __half g_q[MTOK * HIDDEN];        // fp16 Q (pre-scaled)
__device__ __half g_k[MTOK * HIDDEN];        // fp16 K
__device__ __half g_v[MTOK * HIDDEN];        // fp16 V
__device__ __half g_ao[MTOK * HIDDEN];       // attention out fp16
__device__ __half g_hs[MTOK * HIDDEN];       // fp16 hidden states
__device__ __half g_wq[HIDDEN * HIDDEN];     // fp16(scale*wq)^T  [N][K]
__device__ __half g_wk[HIDDEN * HIDDEN];
__device__ __half g_wv[HIDDEN * HIDDEN];
__device__ __half g_wo[HIDDEN * HIDDEN];
__device__ float  g_bqs[HIDDEN];             // scale * bq

__device__ __forceinline__ void mma_f16(float* c, const uint32_t* a, const uint32_t* b) {
    asm volatile(
        "mma.sync.aligned.m16n8k16.row.col.f32.f16.f16.f32 "
        "{%0,%1,%2,%3}, {%4,%5,%6,%7}, {%8,%9}, {%0,%1,%2,%3};\n"
        : "+f"(c[0]), "+f"(c[1]), "+f"(c[2]), "+f"(c[3])
        : "r"(a[0]), "r"(a[1]), "r"(a[2]), "r"(a[3]), "r"(b[0]), "r"(b[1]));
}

__device__ __forceinline__ void ldsm_x4(uint32_t& r0, uint32_t& r1,
                                        uint32_t& r2, uint32_t& r3, uint32_t addr) {
    asm volatile("ldmatrix.sync.aligned.m8n8.x4.shared.b16 {%0,%1,%2,%3}, [%4];"
                 : "=r"(r0), "=r"(r1), "=r"(r2), "=r"(r3) : "r"(addr));
}

__device__ __forceinline__ void ldsm_x2_trans(uint32_t& r0, uint32_t& r1, uint32_t addr) {
    asm volatile("ldmatrix.sync.aligned.m8n8.x2.trans.shared.b16 {%0,%1}, [%2];"
                 : "=r"(r0), "=r"(r1) : "r"(addr));
}

__device__ __forceinline__ void cp_async16(uint32_t smem_addr, const void* gptr) {
    asm volatile("cp.async.cg.shared.global [%0], [%1], 16;"
                 :: "r"(smem_addr), "l"(gptr));
}
#define CP_COMMIT() asm volatile("cp.async.commit_group;" ::: "memory")
#define CP_WAIT(N)  asm volatile("cp.async.wait_group %0;" :: "n"(N) : "memory")

__device__ __forceinline__ uint32_t smem_u32(const void* p) {
    return (uint32_t)__cvta_generic_to_shared(p);
}

// ---------------------------------------------------------------------------
// Prep kernels
// ---------------------------------------------------------------------------
__global__ void prep_round_half(const float* __restrict__ src,
                                __half* __restrict__ dst,
                                float mul, int n4)
{
    int i = blockIdx.x * blockDim.x + threadIdx.x;
    if (i < n4) {
        float4 v = *(const float4*)(src + i * 4);
        *(__half2*)(dst + i * 4)     = __floats2half2_rn(v.x * mul, v.y * mul);
        *(__half2*)(dst + i * 4 + 2) = __floats2half2_rn(v.z * mul, v.w * mul);
    }
}

__global__ void prep_scale_kernel(const float* __restrict__ src,
                                  float* __restrict__ dst,
                                  float mul, int n4)
{
    int i = blockIdx.x * blockDim.x + threadIdx.x;
    if (i < n4) {
        float4 v = *(const float4*)(src + i * 4);
        float4 o = { v.x * mul, v.y * mul, v.z * mul, v.w * mul };
        *(float4*)(dst + i * 4) = o;
    }
}

// Fused: 4 weight transposes W[K][N] -> Wt[N][K] fp16, z selects which.
__global__ void prep_transpose4_half(const float* __restrict__ s0,
                                     const float* __restrict__ s1,
                                     const float* __restrict__ s2,
                                     const float* __restrict__ s3,
                                     __half* __restrict__ d0,
                                     __half* __restrict__ d1,
                                     __half* __restrict__ d2,
                                     __half* __restrict__ d3,
                                     float mul0)
{
    const float* src; __half* dst; float mul;
    switch (blockIdx.z) {
        case 0:  src = s0; dst = d0; mul = mul0; break;
        case 1:  src = s1; dst = d1; mul = 1.0f; break;
        case 2:  src = s2; dst = d2; mul = 1.0f; break;
        default: src = s3; dst = d3; mul = 1.0f; break;
    }
    __shared__ float t[32][33];
    int bx = blockIdx.x * 32, by = blockIdx.y * 32;
    int tx = threadIdx.x, ty = threadIdx.y;
#pragma unroll
    for (int j = 0; j < 4; j++)
        t[ty + 8 * j][tx] = src[(size_t)(by + ty + 8 * j) * HIDDEN + bx + tx];
    __syncthreads();
#pragma unroll
    for (int j = 0; j < 4; j++)
        dst[(size_t)(bx + ty + 8 * j) * HIDDEN + by + tx] =
            __float2half_rn(t[tx][ty + 8 * j] * mul);
}

// ---------------------------------------------------------------------------
// FP16 tensor-core GEMM core (128x128x64 tile, 256 thr, 2 CTA/SM, 2-stage)
// ---------------------------------------------------------------------------
#define GBM 128
#define GBN 128
#define GBK 64
#define GRS 36
#define GRB (GRS * 4)                      // 144 B row stride
#define G_STG_WORDS (GBM * GRS)
#define GEMM_SMEM_BYTES (4 * G_STG_WORDS * 4)   // 73728

template <bool HALF_OUT>
__device__ __forceinline__
void gemm_f16_body(const __half* __restrict__ A,
                   const __half* __restrict__ Wt,
                   const float* __restrict__ bias,
                   float* __restrict__ Cf,
                   __half* __restrict__ Ch,
                   int bm, int bn)
{
    extern __shared__ uint32_t gsm[];
    uint32_t* Asm = gsm;
    uint32_t* Bsm = gsm + 2 * G_STG_WORDS;
    const uint32_t as_u32 = smem_u32(Asm);
    const uint32_t bs_u32 = smem_u32(Bsm);

    const int tid  = threadIdx.x;
    const int lane = tid & 31;
    const int warp = tid >> 5;
    const int wm   = warp >> 2;
    const int wn   = warp & 3;
    const int g    = lane >> 2;
    const int tig  = lane & 3;

    const int gl      = lane & 7;
    const int a_roff  = ((lane >> 3) & 1) * 8 + gl;
    const int a_coff  = (lane >> 4) * 16;
    const int b_roff  = (lane >> 4) * 8 + gl;
    const int b_coff  = ((lane >> 3) & 1) * 16;

    const int f_row = tid >> 1;
    const int f_ch0 = (tid & 1) * 4;

    auto fill = [&](int kt) {
        const int s = kt & 1;
        const __half* Ag = A  + (size_t)bm * HIDDEN + kt * GBK;
        const __half* Bg = Wt + (size_t)bn * HIDDEN + kt * GBK;
        const uint32_t abase = as_u32 + s * G_STG_WORDS * 4;
        const uint32_t bbase = bs_u32 + s * G_STG_WORDS * 4;
#pragma unroll
        for (int c = 0; c < 4; c++) {
            int ch = f_ch0 + c;
            cp_async16(abase + f_row * GRB + ch * 16,
                       Ag + (size_t)f_row * HIDDEN + ch * 8);
            cp_async16(bbase + f_row * GRB + ch * 16,
                       Bg + (size_t)f_row * HIDDEN + ch * 8);
        }
        CP_COMMIT();
    };

    float acc[4][4][4];
#pragma unroll
    for (int mi = 0; mi < 4; mi++)
#pragma unroll
        for (int ni = 0; ni < 4; ni++)
#pragma unroll
            for (int r = 0; r < 4; r++) acc[mi][ni][r] = 0.0f;

    const int nk = HIDDEN / GBK;   // 32
    fill(0);

    for (int kt = 0; kt < nk; kt++) {
        if (kt + 1 < nk) { fill(kt + 1); CP_WAIT(1); }
        else             { CP_WAIT(0); }
        __syncthreads();

        const uint32_t abase = as_u32 + (kt & 1) * G_STG_WORDS * 4;
        const uint32_t bbase = bs_u32 + (kt & 1) * G_STG_WORDS * 4;
#pragma unroll
        for (int ks = 0; ks < 4; ks++) {
            const int kb = ks * 32;
            uint32_t af[4][4], bf[4][2];
#pragma unroll
            for (int mi = 0; mi < 4; mi++) {
                int m = wm * 64 + mi * 16;
                ldsm_x4(af[mi][0], af[mi][1], af[mi][2], af[mi][3],
                        abase + (m + a_roff) * GRB + kb + a_coff);
            }
#pragma unroll
            for (int p = 0; p < 2; p++) {
                int n = wn * 32 + p * 16;
                ldsm_x4(bf[2 * p][0], bf[2 * p][1], bf[2 * p + 1][0], bf[2 * p + 1][1],
                        bbase + (n + b_roff) * GRB + kb + b_coff);
            }
#pragma unroll
            for (int mi = 0; mi < 4; mi++)
#pragma unroll
                for (int ni = 0; ni < 4; ni++)
                    mma_f16(acc[mi][ni], af[mi], bf[ni]);
        }
        __syncthreads();
    }

#pragma unroll
    for (int ni = 0; ni < 4; ni++) {
        int col = bn + wn * 32 + ni * 8 + tig * 2;
        float b0 = bias[col], b1 = bias[col + 1];
#pragma unroll
        for (int mi = 0; mi < 4; mi++) {
            int row = bm + wm * 64 + mi * 16 + g;
            float v00 = acc[mi][ni][0] + b0, v01 = acc[mi][ni][1] + b1;
            float v10 = acc[mi][ni][2] + b0, v11 = acc[mi][ni][3] + b1;
            if (HALF_OUT) {
                *(__half2*)(Ch + (size_t)row * HIDDEN + col)       = __floats2half2_rn(v00, v01);
                *(__half2*)(Ch + (size_t)(row + 8) * HIDDEN + col) = __floats2half2_rn(v10, v11);
            } else {
                float2 r0 = { v00, v01 };
                float2 r1 = { v10, v11 };
                *(float2*)(Cf + (size_t)row * HIDDEN + col)       = r0;
                *(float2*)(Cf + (size_t)(row + 8) * HIDDEN + col) = r1;
            }
        }
    }
}

// Fused QKV: grid.z in {0,1,2} selects weight/bias/output.
__global__ __launch_bounds__(256, 2)
void gemm_qkv_kernel(const __half* __restrict__ A,
                     const __half* __restrict__ w0, const __half* __restrict__ w1,
                     const __half* __restrict__ w2,
                     const float* __restrict__ b0, const float* __restrict__ b1,
                     const float* __restrict__ b2,
                     __half* __restrict__ c0, __half* __restrict__ c1,
                     __half* __restrict__ c2)
{
    const __half* Wt; const float* bias; __half* Ch;
    switch (blockIdx.z) {
        case 0:  Wt = w0; bias = b0; Ch = c0; break;
        case 1:  Wt = w1; bias = b1; Ch = c1; break;
        default: Wt = w2; bias = b2; Ch = c2; break;
    }
    gemm_f16_body<true>(A, Wt, bias, nullptr, Ch,
                        blockIdx.y * GBM, blockIdx.x * GBN);
}

// O-projection: fp32 output.
__global__ __launch_bounds__(256, 2)
void gemm_out_kernel(const __half* __restrict__ A,
                     const __half* __restrict__ Wt,
                     const float* __restrict__ bias,
                     float* __restrict__ Cf)
{
    gemm_f16_body<false>(A, Wt, bias, Cf, nullptr,
                         blockIdx.y * GBM, blockIdx.x * GBN);
}

// ---------------------------------------------------------------------------
// FP16 tensor-core flash attention (round-15 proven), 256 thr, BQ=128, BKV=64.
// ---------------------------------------------------------------------------
#define ABQ 128
#define ABKV 64
#define LQK 68    // Q/K row stride, u32 words (272 B)
#define LVW 68    // V row stride
#define LPW 36    // P row stride (144 B)

#define AS_QS 0
#define AS_KS (AS_QS + ABQ * LQK)         // 8704
#define AS_VS (AS_KS + ABKV * LQK)        // 13056
#define AS_PS (AS_VS + ABKV * LVW)        // 17408
#define AS_MB (AS_PS + ABQ * LPW)         // 22016
#define AS_LB (AS_MB + 2 * ABQ)           // 22272
#define AS_TOT (AS_LB + 2 * ABQ)          // 22528 words
#define ATTN_SMEM_BYTES (AS_TOT * 4)      // 90112 B

__global__ __launch_bounds__(256)
void attn_f16_kernel(const __half* __restrict__ Q,
                     const __half* __restrict__ K,
                     const __half* __restrict__ V,
                     __half* __restrict__ O)
{
    extern __shared__ float sm[];
    uint32_t* Pu = (uint32_t*)(sm + AS_PS);
    float* maxbuf = sm + AS_MB;
    float* lbuf   = sm + AS_LB;
    const uint32_t qs_u32 = smem_u32(sm + AS_QS);
    const uint32_t ks_u32 = smem_u32(sm + AS_KS);
    const uint32_t vs_u32 = smem_u32(sm + AS_VS);
    const uint32_t ps_u32 = smem_u32(sm + AS_PS);

    const int tid  = threadIdx.x;
    const int lane = tid & 31;
    const int warp = tid >> 5;
    const int g    = lane >> 2;
    const int tig  = lane & 3;
    const int wm   = warp >> 1;    // 0..3 -> q rows wm*32
    const int wn   = warp & 1;     // 0..1 -> kv slab (S) / d slab (PV)

    const int q0 = blockIdx.x * ABQ;
    const int h  = blockIdx.y;
    const int b  = blockIdx.z;
    const size_t base = (size_t)b * SEQ * HIDDEN + (size_t)h * HEADDIM;

    const int rowA0 = wm * 32 + g;
    float mreg[4] = { -INFINITY, -INFINITY, -INFINITY, -INFINITY };
    float lreg[4] = { 0.0f, 0.0f, 0.0f, 0.0f };

    const int gl     = lane & 7;
    const int a_roff = ((lane >> 3) & 1) * 8 + gl;
    const int a_coff = (lane >> 4) * 16;
    const int b_roff = (lane >> 4) * 8 + gl;
    const int b_coff = ((lane >> 3) & 1) * 16;

    const int qrow = tid >> 1, qch0 = (tid & 1) * 8;
    const int krow = tid >> 2, kch0 = (tid & 3) * 4;

    // ---- prologue: Q, K(0), V(0) ----
#pragma unroll
    for (int c = 0; c < 8; c++)
        cp_async16(qs_u32 + qrow * (LQK * 4) + (qch0 + c) * 16,
                   Q + base + (size_t)(q0 + qrow) * HIDDEN + (qch0 + c) * 8);
    CP_COMMIT();
#pragma unroll
    for (int c = 0; c < 4; c++)
        cp_async16(ks_u32 + krow * (LQK * 4) + (kch0 + c) * 16,
                   K + base + (size_t)krow * HIDDEN + (kch0 + c) * 8);
    CP_COMMIT();
#pragma unroll
    for (int c = 0; c < 4; c++)
        cp_async16(vs_u32 + krow * (LVW * 4) + (kch0 + c) * 16,
                   V + base + (size_t)krow * HIDDEN + (kch0 + c) * 8);
    CP_COMMIT();

    float o[2][8][4];
#pragma unroll
    for (int mi = 0; mi < 2; mi++)
#pragma unroll
        for (int nj = 0; nj < 8; nj++)
#pragma unroll
            for (int r = 0; r < 4; r++) o[mi][nj][r] = 0.0f;

    const int NT = SEQ / ABKV;   // 32
    for (int t = 0; t < NT; t++) {
        CP_WAIT(1);
        __syncthreads();

        // ---- S = Q @ K^T : warp tile 32x32, 8 k-steps, ldmatrix frags ----
        float sacc[2][4][4];
#pragma unroll
        for (int mi = 0; mi < 2; mi++)
#pragma unroll
            for (int ni = 0; ni < 4; ni++)
#pragma unroll
                for (int r = 0; r < 4; r++) sacc[mi][ni][r] = 0.0f;

#pragma unroll
        for (int ks = 0; ks < 8; ks++) {
            const int kb = ks * 32;
            uint32_t af[2][4], bf[4][2];
#pragma unroll
            for (int mi = 0; mi < 2; mi++) {
                int m = wm * 32 + mi * 16;
                ldsm_x4(af[mi][0], af[mi][1], af[mi][2], af[mi][3],
                        qs_u32 + (m + a_roff) * (LQK * 4) + kb + a_coff);
            }
#pragma unroll
            for (int p = 0; p < 2; p++) {
                int n = wn * 32 + p * 16;
                ldsm_x4(bf[2 * p][0], bf[2 * p][1], bf[2 * p + 1][0], bf[2 * p + 1][1],
                        ks_u32 + (n + b_roff) * (LQK * 4) + kb + b_coff);
            }
#pragma unroll
            for (int mi = 0; mi < 2; mi++)
#pragma unroll
                for (int ni = 0; ni < 4; ni++)
                    mma_f16(sacc[mi][ni], af[mi], bf[ni]);
        }

        // ---- warp-local row maxes ----
#pragma unroll
        for (int mi = 0; mi < 2; mi++) {
            float a = -INFINITY, c = -INFINITY;
#pragma unroll
            for (int ni = 0; ni < 4; ni++) {
                a = fmaxf(a, fmaxf(sacc[mi][ni][0], sacc[mi][ni][1]));
                c = fmaxf(c, fmaxf(sacc[mi][ni][2], sacc[mi][ni][3]));
            }
            a = fmaxf(a, __shfl_xor_sync(0xFFFFFFFF, a, 1));
            a = fmaxf(a, __shfl_xor_sync(0xFFFFFFFF, a, 2));
            c = fmaxf(c, __shfl_xor_sync(0xFFFFFFFF, c, 1));
            c = fmaxf(c, __shfl_xor_sync(0xFFFFFFFF, c, 2));
            if (tig == 0) {
                maxbuf[wn * ABQ + rowA0 + mi * 16]     = a;
                maxbuf[wn * ABQ + rowA0 + mi * 16 + 8] = c;
            }
        }
        __syncthreads();   // Ks consumed + maxbuf visible

        // ---- prefetch K(t+1) ----
        if (t + 1 < NT) {
            const __half* Kn = K + base + (size_t)(t + 1) * ABKV * HIDDEN;
#pragma unroll
            for (int c = 0; c < 4; c++)
                cp_async16(ks_u32 + krow * (LQK * 4) + (kch0 + c) * 16,
                           Kn + (size_t)krow * HIDDEN + (kch0 + c) * 8);
            CP_COMMIT();
        }

        // ---- softmax: combine maxes, exp, write P (fp16) ----
        float sc[4], lsum[4];
#pragma unroll
        for (int i = 0; i < 4; i++) {
            int row = rowA0 + (i >> 1) * 16 + (i & 1) * 8;
            float mn = fmaxf(mreg[i], fmaxf(maxbuf[row], maxbuf[ABQ + row]));
            sc[i] = __expf(mreg[i] - mn);
            mreg[i] = mn;
            lsum[i] = 0.0f;
        }
#pragma unroll
        for (int mi = 0; mi < 2; mi++) {
            int rA = rowA0 + mi * 16;
#pragma unroll
            for (int ni = 0; ni < 4; ni++) {
                int cw = wn * 16 + ni * 4 + tig;
                __half2 h0 = __floats2half2_rn(__expf(sacc[mi][ni][0] - mreg[mi * 2]),
                                               __expf(sacc[mi][ni][1] - mreg[mi * 2]));
                __half2 h1 = __floats2half2_rn(__expf(sacc[mi][ni][2] - mreg[mi * 2 + 1]),
                                               __expf(sacc[mi][ni][3] - mreg[mi * 2 + 1]));
                float2 f0 = __half22float2(h0);
                float2 f1 = __half22float2(h1);
                lsum[mi * 2]     += f0.x + f0.y;
                lsum[mi * 2 + 1] += f1.x + f1.y;
                Pu[rA * LPW + cw]       = *(uint32_t*)&h0;
                Pu[(rA + 8) * LPW + cw] = *(uint32_t*)&h1;
            }
        }
#pragma unroll
        for (int i = 0; i < 4; i++) {
            float ls = lsum[i];
            ls += __shfl_xor_sync(0xFFFFFFFF, ls, 1);
            ls += __shfl_xor_sync(0xFFFFFFFF, ls, 2);
            lsum[i] = ls;
        }
        if (tig == 0) {
#pragma unroll
            for (int i = 0; i < 4; i++) {
                int row = rowA0 + (i >> 1) * 16 + (i & 1) * 8;
                lbuf[wn * ABQ + row] = lsum[i];
            }
        }

        if (t + 1 < NT) { CP_WAIT(1); } else { CP_WAIT(0); }
        __syncthreads();   // P + lbuf visible, Vs(t) resident

#pragma unroll
        for (int i = 0; i < 4; i++) {
            int row = rowA0 + (i >> 1) * 16 + (i & 1) * 8;
            lreg[i] = lreg[i] * sc[i] + lbuf[row] + lbuf[ABQ + row];
        }

        // ---- O rescale + O += P @ V : warp tile 32x64, 4 k-steps ----
#pragma unroll
        for (int mi = 0; mi < 2; mi++) {
            float s0 = sc[mi * 2], s1 = sc[mi * 2 + 1];
#pragma unroll
            for (int nj = 0; nj < 8; nj++) {
                o[mi][nj][0] *= s0; o[mi][nj][1] *= s0;
                o[mi][nj][2] *= s1; o[mi][nj][3] *= s1;
            }
        }
#pragma unroll
        for (int ks = 0; ks < 4; ks++) {
            const int kb = ks * 32;          // P byte offset (16 halves)
            const int kv0 = ks * 16;         // V row
            uint32_t af[2][4], bf[8][2];
#pragma unroll
            for (int mi = 0; mi < 2; mi++) {
                int m = wm * 32 + mi * 16;
                ldsm_x4(af[mi][0], af[mi][1], af[mi][2], af[mi][3],
                        ps_u32 + (m + a_roff) * (LPW * 4) + kb + a_coff);
            }
            const uint32_t vrow_addr = vs_u32 + (kv0 + (lane & 15)) * (LVW * 4);
#pragma unroll
            for (int nj = 0; nj < 8; nj++) {
                int n = wn * 64 + nj * 8;
                ldsm_x2_trans(bf[nj][0], bf[nj][1], vrow_addr + n * 2);
            }
#pragma unroll
            for (int mi = 0; mi < 2; mi++)
#pragma unroll
                for (int nj = 0; nj < 8; nj++)
                    mma_f16(o[mi][nj], af[mi], bf[nj]);
        }
        __syncthreads();   // Vs consumed

        // ---- prefetch V(t+1) ----
        if (t + 1 < NT) {
            const __half* Vn = V + base + (size_t)(t + 1) * ABKV * HIDDEN;
#pragma unroll
            for (int c = 0; c < 4; c++)
                cp_async16(vs_u32 + krow * (LVW * 4) + (kch0 + c) * 16,
                           Vn + (size_t)krow * HIDDEN + (kch0 + c) * 8);
            CP_COMMIT();
        }
    }

    // ---- Epilogue: normalize, store fp16 ----
#pragma unroll
    for (int mi = 0; mi < 2; mi++) {
        int r0 = wm * 32 + mi * 16 + g;
        float inv0 = 1.0f / lreg[mi * 2];
        float inv1 = 1.0f / lreg[mi * 2 + 1];
#pragma unroll
        for (int nj = 0; nj < 8; nj++) {
            int col = wn * 64 + nj * 8 + tig * 2;
            __half2 a = __floats2half2_rn(o[mi][nj][0] * inv0, o[mi][nj][1] * inv0);
            __half2 c = __floats2half2_rn(o[mi][nj][2] * inv1, o[mi][nj][3] * inv1);
            *(__half2*)(O + base + (size_t)(q0 + r0) * HIDDEN + col)     = a;
            *(__half2*)(O + base + (size_t)(q0 + r0 + 8) * HIDDEN + col) = c;
        }
    }
}

// ---------------------------------------------------------------------------
// Launch
// ---------------------------------------------------------------------------
extern "C" void kernel_launch(void* const* d_in, const int* in_sizes, int n_in,
                              void* d_out, int out_size)
{
    (void)in_sizes; (void)n_in; (void)out_size;

    const float* hs = (const float*)d_in[0];
    const float* wq = (const float*)d_in[1];
    const float* bq = (const float*)d_in[2];
    const float* wk = (const float*)d_in[3];
    const float* bk = (const float*)d_in[4];
    const float* wv = (const float*)d_in[5];
    const float* bv = (const float*)d_in[6];
    const float* wo = (const float*)d_in[7];
    const float* bo = (const float*)d_in[8];
    float* out = (float*)d_out;

    float *bqs;
    __half *q, *k, *v, *ao, *hsr, *wqr, *wkr, *wvr, *wor;
    cudaGetSymbolAddress((void**)&q,   g_q);
    cudaGetSymbolAddress((void**)&k,   g_k);
    cudaGetSymbolAddress((void**)&v,   g_v);
    cudaGetSymbolAddress((void**)&ao,  g_ao);
    cudaGetSymbolAddress((void**)&hsr, g_hs);
    cudaGetSymbolAddress((void**)&wqr, g_wq);
    cudaGetSymbolAddress((void**)&wkr, g_wk);
    cudaGetSymbolAddress((void**)&wvr, g_wv);
    cudaGetSymbolAddress((void**)&wor, g_wo);
    cudaGetSymbolAddress((void**)&bqs, g_bqs);

    cudaFuncSetAttribute(attn_f16_kernel,
                         cudaFuncAttributeMaxDynamicSharedMemorySize,
                         ATTN_SMEM_BYTES);
    cudaFuncSetAttribute(gemm_qkv_kernel,
                         cudaFuncAttributeMaxDynamicSharedMemorySize,
                         GEMM_SMEM_BYTES);
    cudaFuncSetAttribute(gemm_out_kernel,
                         cudaFuncAttributeMaxDynamicSharedMemorySize,
                         GEMM_SMEM_BYTES);

    const float scale = 0.08838834764831845f;  // 1/sqrt(128)

    // ---- prep: hs round, fused weight transposes, bq scale ----
    const int nh4 = MTOK * HIDDEN / 4;
    prep_round_half<<<nh4 / 256, 256>>>(hs, hsr, 1.0f, nh4);
    dim3 tgrid(HIDDEN / 32, HIDDEN / 32, 4), tblk(32, 8);
    prep_transpose4_half<<<tgrid, tblk>>>(wq, wk, wv, wo,
                                          wqr, wkr, wvr, wor, scale);
    prep_scale_kernel<<<HIDDEN / 4 / 64, 64>>>(bq, bqs, scale, HIDDEN / 4);

    // ---- fused QKV projections (one launch, grid.z = 3) ----
    dim3 qkv_grid(HIDDEN / GBN, MTOK / GBM, 3);   // (16, 32, 3)
    gemm_qkv_kernel<<<qkv_grid, 256, GEMM_SMEM_BYTES>>>(
        hsr, wqr, wkr, wvr, bqs, bk, bv, q, k, v);

    // ---- attention ----
    dim3 attn_grid(SEQ / ABQ, NHEADS, BATCH);     // (16, 16, 2)
    attn_f16_kernel<<<attn_grid, 256, ATTN_SMEM_BYTES>>>(q, k, v, ao);

    // ---- output projection ----
    dim3 gemm_grid(HIDDEN / GBN, MTOK / GBM);     // (16, 32)
    gemm_out_kernel<<<gemm_grid, 256, GEMM_SMEM_BYTES>>>(ao, wor, bo, out);
}